// round 13
// baseline (speedup 1.0000x reference)
#include <cuda_runtime.h>

// Problem constants
#define BT     16384
#define S_DIM  256
#define O_DIM  128
#define N_DIM  32
#define NQ_DIM 64
#define NOUT   160
#define MASK_VAL (-999999.0f)
#define INV_SQRT_E 0.17677669529663687f

typedef unsigned long long ull;

// Scratch (device globals; no allocation allowed)
__device__ float g_qp0[(size_t)BT * NOUT];   // K1 raw partials, K-half 0
__device__ float g_qp1[(size_t)BT * NOUT];   // K1 raw partials, K-half 1
__device__ float g_v[BT];
__device__ float g_p[(size_t)BT * 512];

// ---------------- packed f32x2 helpers ----------------
static __device__ __forceinline__ ull fma2(ull a, ull b, ull c) {
    ull d;
    asm("fma.rn.f32x2 %0, %1, %2, %3;" : "=l"(d) : "l"(a), "l"(b), "l"(c));
    return d;
}
static __device__ __forceinline__ ull dup2(float w) {
    ull d;
    asm("mov.b64 %0, {%1, %1};" : "=l"(d) : "f"(w));
    return d;
}
static __device__ __forceinline__ ull pack2(float x, float y) {
    ull d;
    asm("mov.b64 %0, {%1, %2};" : "=l"(d) : "f"(x), "f"(y));
    return d;
}
static __device__ __forceinline__ float lo2(ull v) {
    return __uint_as_float((unsigned int)v);
}
static __device__ __forceinline__ float hi2(ull v) {
    return __uint_as_float((unsigned int)(v >> 32));
}

// ---------------- cp.async helpers ----------------
static __device__ __forceinline__ void cp16(void* dst, const void* src) {
    unsigned s = (unsigned)__cvta_generic_to_shared(dst);
    asm volatile("cp.async.cg.shared.global [%0], [%1], 16;" :: "r"(s), "l"(src));
}
static __device__ __forceinline__ void cp4(void* dst, const void* src) {
    unsigned s = (unsigned)__cvta_generic_to_shared(dst);
    asm volatile("cp.async.ca.shared.global [%0], [%1], 4;" :: "r"(s), "l"(src));
}
#define CP_COMMIT() asm volatile("cp.async.commit_group;")
#define CP_WAIT1()  asm volatile("cp.async.wait_group 1;")
#define CP_WAIT0()  asm volatile("cp.async.wait_group 0;")

// ==================== K1: raw partials over a K=128 half ====================
// grid = 512 (256 row-tiles x 2 K-halves). Same proven inner loop as R9,
// epilogue stores raw accumulators (relu/bias moved to K2).
#define K1_BM 64
#define K1_KC 32
#define K1_AS 66
#define K1_WS 33
#define K1_SMEM (K1_KC*K1_AS*4 + NOUT*K1_WS*4)   // 29568B

__global__ void __launch_bounds__(256, 2) k1_qh(
        const float* __restrict__ st,
        const float* __restrict__ Wq,
        const float* __restrict__ Sw1) {
    extern __shared__ float smem[];
    float* As = smem;                          // [32 k][66]
    float* Ws = smem + K1_KC * K1_AS;          // [160 n][33]

    const int tid = threadIdx.x;
    const int rt  = tid >> 5;
    const int ct  = tid & 31;
    const int half = blockIdx.x & 1;
    const int row0 = (blockIdx.x >> 1) * K1_BM;
    float* dst = half ? g_qp1 : g_qp0;

    const float* wp0 = Ws + (ct)       * K1_WS;
    const float* wp1 = Ws + (ct + 32)  * K1_WS;
    const float* wp2 = Ws + (ct + 64)  * K1_WS;
    const float* wp3 = Ws + (ct + 96)  * K1_WS;
    const float* wp4 = Ws + (ct + 128) * K1_WS;

    ull acc[4][5];
#pragma unroll
    for (int i = 0; i < 4; i++)
#pragma unroll
        for (int j = 0; j < 5; j++) acc[i][j] = 0ULL;

    const int kc0 = half * 128;
    for (int kc = kc0; kc < kc0 + 128; kc += K1_KC) {
        __syncthreads();
#pragma unroll
        for (int s = 0; s < 2; s++) {
            int idx = tid + 256 * s;
            int row = idx >> 3, kq = idx & 7;
            float4 v = *(const float4*)(st + (size_t)(row0 + row) * S_DIM + kc + 4 * kq);
            As[(4 * kq + 0) * K1_AS + row] = v.x;
            As[(4 * kq + 1) * K1_AS + row] = v.y;
            As[(4 * kq + 2) * K1_AS + row] = v.z;
            As[(4 * kq + 3) * K1_AS + row] = v.w;
        }
        for (int i = tid; i < (NOUT * K1_KC) / 4; i += 256) {
            int n = i >> 3, kq = i & 7;
            const float* src = (n < 128) ? (Wq + n * S_DIM) : (Sw1 + (n - 128) * S_DIM);
            float4 v = *(const float4*)(src + kc + 4 * kq);
            Ws[n * K1_WS + 4 * kq + 0] = v.x;
            Ws[n * K1_WS + 4 * kq + 1] = v.y;
            Ws[n * K1_WS + 4 * kq + 2] = v.z;
            Ws[n * K1_WS + 4 * kq + 3] = v.w;
        }
        __syncthreads();

        float c0 = wp0[0], c1 = wp1[0], c2 = wp2[0], c3 = wp3[0], c4 = wp4[0];
        const float* ar0 = As + rt * 8;
        ull a0 = *(const ull*)(ar0);
        ull a1 = *(const ull*)(ar0 + 2);
        ull a2 = *(const ull*)(ar0 + 4);
        ull a3 = *(const ull*)(ar0 + 6);
#pragma unroll
        for (int kk = 0; kk < K1_KC; kk++) {
            float d0, d1, d2, d3, d4;
            ull e0, e1, e2, e3;
            if (kk < K1_KC - 1) {
                d0 = wp0[kk + 1]; d1 = wp1[kk + 1]; d2 = wp2[kk + 1];
                d3 = wp3[kk + 1]; d4 = wp4[kk + 1];
                const float* arn = As + (kk + 1) * K1_AS + rt * 8;
                e0 = *(const ull*)(arn);
                e1 = *(const ull*)(arn + 2);
                e2 = *(const ull*)(arn + 4);
                e3 = *(const ull*)(arn + 6);
            } else {
                d0 = d1 = d2 = d3 = d4 = 0.0f;
                e0 = e1 = e2 = e3 = 0ULL;
            }
            ull b0 = dup2(c0), b1 = dup2(c1), b2 = dup2(c2),
                b3 = dup2(c3), b4 = dup2(c4);
            acc[0][0] = fma2(a0, b0, acc[0][0]);
            acc[1][0] = fma2(a1, b0, acc[1][0]);
            acc[2][0] = fma2(a2, b0, acc[2][0]);
            acc[3][0] = fma2(a3, b0, acc[3][0]);
            acc[0][1] = fma2(a0, b1, acc[0][1]);
            acc[1][1] = fma2(a1, b1, acc[1][1]);
            acc[2][1] = fma2(a2, b1, acc[2][1]);
            acc[3][1] = fma2(a3, b1, acc[3][1]);
            acc[0][2] = fma2(a0, b2, acc[0][2]);
            acc[1][2] = fma2(a1, b2, acc[1][2]);
            acc[2][2] = fma2(a2, b2, acc[2][2]);
            acc[3][2] = fma2(a3, b2, acc[3][2]);
            acc[0][3] = fma2(a0, b3, acc[0][3]);
            acc[1][3] = fma2(a1, b3, acc[1][3]);
            acc[2][3] = fma2(a2, b3, acc[2][3]);
            acc[3][3] = fma2(a3, b3, acc[3][3]);
            acc[0][4] = fma2(a0, b4, acc[0][4]);
            acc[1][4] = fma2(a1, b4, acc[1][4]);
            acc[2][4] = fma2(a2, b4, acc[2][4]);
            acc[3][4] = fma2(a3, b4, acc[3][4]);
            c0 = d0; c1 = d1; c2 = d2; c3 = d3; c4 = d4;
            a0 = e0; a1 = e1; a2 = e2; a3 = e3;
        }
    }

    // raw partial store (coalesced per column group)
#pragma unroll
    for (int i = 0; i < 4; i++) {
        size_t r0 = (size_t)(row0 + rt * 8 + 2 * i);
#pragma unroll
        for (int j = 0; j < 4; j++) {
            dst[r0 * NOUT + ct + 32 * j]       = lo2(acc[i][j]);
            dst[(r0 + 1) * NOUT + ct + 32 * j] = hi2(acc[i][j]);
        }
        dst[r0 * NOUT + 128 + ct]       = lo2(acc[i][4]);
        dst[(r0 + 1) * NOUT + 128 + ct] = hi2(acc[i][4]);
    }
}

// ==================== K2: combine halves (relu + bias MLP), then p GEMM ====================
#define K2_BM 32

__global__ void __launch_bounds__(256) k2_p(
        const float* __restrict__ Wk,
        const float* __restrict__ Sb1,
        const float* __restrict__ Sw2,
        const float* __restrict__ Sb2) {
    __shared__ float qh_s[K2_BM * 128];

    const int tid = threadIdx.x;
    const int rt  = tid >> 5;
    const int ct  = tid & 31;
    const int row0 = blockIdx.x * K2_BM;

    // stage qh = relu(part0 + part1)  (1024 float4)
#pragma unroll
    for (int s = 0; s < 4; s++) {
        int i = tid + 256 * s;
        int row = i >> 5, c4 = i & 31;
        size_t base = (size_t)(row0 + row) * NOUT + 4 * c4;
        float4 a = *(const float4*)(g_qp0 + base);
        float4 b = *(const float4*)(g_qp1 + base);
        float4 v;
        v.x = fmaxf(a.x + b.x, 0.0f);
        v.y = fmaxf(a.y + b.y, 0.0f);
        v.z = fmaxf(a.z + b.z, 0.0f);
        v.w = fmaxf(a.w + b.w, 0.0f);
        ((float4*)qh_s)[i] = v;
    }

    // bias MLP: warp rt handles rows rt*4..rt*4+3, lane = hidden idx
    {
        const float b1l = Sb1[ct];
        const float w2l = Sw2[ct];
        const float b2c = Sb2[0];
#pragma unroll
        for (int rr = 0; rr < 4; rr++) {
            size_t row = (size_t)(row0 + rt * 4 + rr);
            float hv = g_qp0[row * NOUT + 128 + ct] + g_qp1[row * NOUT + 128 + ct];
            float val = fmaxf(hv + b1l, 0.0f) * w2l;
#pragma unroll
            for (int d = 16; d > 0; d >>= 1)
                val += __shfl_xor_sync(0xffffffffu, val, d);
            if (ct == 0) g_v[row] = val + b2c;
        }
    }
    __syncthreads();

    const ull* wkp = (const ull*)Wk;
    ull* gp2 = (ull*)g_p;
#pragma unroll
    for (int h = 0; h < 4; h++) {
        ull acc[4][2];
#pragma unroll
        for (int rr = 0; rr < 4; rr++) { acc[rr][0] = 0ULL; acc[rr][1] = 0ULL; }

#pragma unroll 4
        for (int e4 = 0; e4 < 8; e4++) {
            float4 aq[4];
#pragma unroll
            for (int rr = 0; rr < 4; rr++)
                aq[rr] = *(const float4*)(qh_s + (rt * 4 + rr) * 128 + h * 32 + 4 * e4);
#pragma unroll
            for (int q = 0; q < 4; q++) {
                const ull* brow = wkp + (size_t)(h * 32 + 4 * e4 + q) * 64;
                ull b0 = brow[ct];
                ull b1 = brow[32 + ct];
#pragma unroll
                for (int rr = 0; rr < 4; rr++) {
                    float av = (q == 0) ? aq[rr].x : (q == 1) ? aq[rr].y
                             : (q == 2) ? aq[rr].z : aq[rr].w;
                    ull a = dup2(av);
                    acc[rr][0] = fma2(a, b0, acc[rr][0]);
                    acc[rr][1] = fma2(a, b1, acc[rr][1]);
                }
            }
        }
#pragma unroll
        for (int rr = 0; rr < 4; rr++) {
            size_t base = (size_t)(row0 + rt * 4 + rr) * 256 + h * 64;
            gp2[base + ct]      = acc[rr][0];
            gp2[base + 32 + ct] = acc[rr][1];
        }
    }
}

// ==================== K3: cp.async pipeline + uniform-LDS.64 p + fma2 ====================
#define K3_ROWS 8

struct K3S {
    float4 ob[2][32 * 33];     // ob[n][c] padded 33
    float4 zb[2][32 * 17];     // z[n][jq] padded 17
    float4 pb[2][128];
    float  part_s[4][4][32];
    float  att_s[128];
    float  w_s[32];
    float  qv_s[32];
    float  vbuf[2];
};
#define K3_SMEM ((int)sizeof(K3S))

__global__ void __launch_bounds__(128) k3_out(
        const float* __restrict__ z,
        const float* __restrict__ obs,
        float* __restrict__ out) {
    extern __shared__ char sm3[];
    K3S* S = (K3S*)sm3;

    const int tid = threadIdx.x;
    const size_t r0 = (size_t)blockIdx.x * K3_ROWS;
    const float4* gp4 = (const float4*)g_p;

    auto prefetch = [&](int b, size_t r) {
        const float4* obr4 = (const float4*)(obs + r * (size_t)(N_DIM * O_DIM));
        const float4* zr4  = (const float4*)(z + r * (size_t)(N_DIM * NQ_DIM));
#pragma unroll
        for (int seg = 0; seg < 8; seg++) {
            int i = tid + 128 * seg;
            int n = i >> 5, c = i & 31;
            cp16(&S->ob[b][n * 33 + c], obr4 + i);
        }
#pragma unroll
        for (int seg = 0; seg < 4; seg++) {
            int i = tid + 128 * seg;
            int n = i >> 4, jq = i & 15;
            cp16(&S->zb[b][n * 17 + jq], zr4 + i);
        }
        cp16(&S->pb[b][tid], gp4 + r * 128 + tid);
        if (tid == 0) cp4(&S->vbuf[b], g_v + r);
    };

    prefetch(0, r0);
    CP_COMMIT();

    const int n  = tid & 31;
    const int oq = tid >> 5;

    for (int i = 0; i < K3_ROWS; i++) {
        const int b = i & 1;
        const size_t r = r0 + i;
        if (i + 1 < K3_ROWS) {
            prefetch(b ^ 1, r + 1);
            CP_COMMIT();
            CP_WAIT1();
        } else {
            CP_WAIT0();
        }
        __syncthreads();

        // q_vals (warp 0)
        if (tid < 32) {
            const float4* zrow = &S->zb[b][tid * 17];
            float s = 0.0f;
#pragma unroll
            for (int j = 0; j < 16; j++) {
                float4 v = zrow[j];
                s += v.x + v.y + v.z + v.w;
            }
            S->qv_s[tid] = s * (1.0f / 64.0f);
        }

        // scores: p via warp-uniform LDS.64 pairs, accumulate with fma2
        const ull* pu = (const ull*)S->pb[b];   // pair index = (h*128 + o)/2
        const float4* obn = &S->ob[b][n * 33 + oq * 8];
        ull ac0 = 0ULL, ac1 = 0ULL, ac2 = 0ULL, ac3 = 0ULL;
#pragma unroll
        for (int o4 = 0; o4 < 8; o4++) {
            float4 x = obn[o4];
            ull xa = pack2(x.x, x.y);
            ull xb = pack2(x.z, x.w);
            int pi = oq * 16 + 2 * o4;          // pair index within a head row
            ac0 = fma2(xa, pu[0   + pi], ac0);
            ac0 = fma2(xb, pu[0   + pi + 1], ac0);
            ac1 = fma2(xa, pu[64  + pi], ac1);
            ac1 = fma2(xb, pu[64  + pi + 1], ac1);
            ac2 = fma2(xa, pu[128 + pi], ac2);
            ac2 = fma2(xb, pu[128 + pi + 1], ac2);
            ac3 = fma2(xa, pu[192 + pi], ac3);
            ac3 = fma2(xb, pu[192 + pi + 1], ac3);
        }
        S->part_s[oq][0][n] = lo2(ac0) + hi2(ac0);
        S->part_s[oq][1][n] = lo2(ac1) + hi2(ac1);
        S->part_s[oq][2][n] = lo2(ac2) + hi2(ac2);
        S->part_s[oq][3][n] = lo2(ac3) + hi2(ac3);
        __syncthreads();

        // softmax per head-warp (h = oq)
        const int h = oq;
        float s = S->part_s[0][h][n] + S->part_s[1][h][n]
                + S->part_s[2][h][n] + S->part_s[3][h][n];
        s *= INV_SQRT_E;
        if (S->qv_s[n] <= MASK_VAL) s = MASK_VAL;
        float m = s;
#pragma unroll
        for (int d = 16; d > 0; d >>= 1) m = fmaxf(m, __shfl_xor_sync(0xffffffffu, m, d));
        float ex = __expf(s - m);
        float ssum = ex;
#pragma unroll
        for (int d = 16; d > 0; d >>= 1) ssum += __shfl_xor_sync(0xffffffffu, ssum, d);
        S->att_s[h * 32 + n] = ex / ssum;
        __syncthreads();

        if (tid < 32)
            S->w_s[tid] = S->att_s[tid] + S->att_s[32 + tid]
                        + S->att_s[64 + tid] + S->att_s[96 + tid] + 1e-10f;
        __syncthreads();

        if (tid < 64) {
            const float* zsf = (const float*)S->zb[b];
            float acc = (float)N_DIM * S->vbuf[b];
#pragma unroll
            for (int nn = 0; nn < 32; nn++)
                acc = fmaf(S->w_s[nn], zsf[nn * 68 + tid], acc);
            out[r * 64 + tid] = acc;
        }
        __syncthreads();
    }
}

// ==================== launch ====================
extern "C" void kernel_launch(void* const* d_in, const int* in_sizes, int n_in,
                              void* d_out, int out_size) {
    (void)in_sizes; (void)n_in; (void)out_size;
    const float* z   = (const float*)d_in[0];
    const float* st  = (const float*)d_in[1];
    const float* obs = (const float*)d_in[2];
    const float* Wq  = (const float*)d_in[3];
    const float* Wk  = (const float*)d_in[4];
    const float* Sw1 = (const float*)d_in[5];
    const float* Sb1 = (const float*)d_in[6];
    const float* Sw2 = (const float*)d_in[7];
    const float* Sb2 = (const float*)d_in[8];
    float* out = (float*)d_out;

    cudaFuncSetAttribute(k1_qh,  cudaFuncAttributeMaxDynamicSharedMemorySize, K1_SMEM);
    cudaFuncSetAttribute(k3_out, cudaFuncAttributeMaxDynamicSharedMemorySize, K3_SMEM);

    k1_qh<<<(BT / K1_BM) * 2, 256, K1_SMEM>>>(st, Wq, Sw1);
    k2_p<<<BT / K2_BM, 256>>>(Wk, Sb1, Sw2, Sb2);
    k3_out<<<BT / K3_ROWS, 128, K3_SMEM>>>(z, obs, out);
}

// round 14
// speedup vs baseline: 1.0024x; 1.0024x over previous
#include <cuda_runtime.h>

// Problem constants
#define BT     16384
#define S_DIM  256
#define O_DIM  128
#define N_DIM  32
#define NQ_DIM 64
#define NOUT   160
#define MASK_VAL (-999999.0f)
#define INV_SQRT_E 0.17677669529663687f

typedef unsigned long long ull;

// Scratch (device globals; no allocation allowed)
__device__ float g_qh[(size_t)BT * 128];
__device__ float g_v[BT];
__device__ float g_p[(size_t)BT * 512];

// ---------------- packed f32x2 helpers ----------------
static __device__ __forceinline__ ull fma2(ull a, ull b, ull c) {
    ull d;
    asm("fma.rn.f32x2 %0, %1, %2, %3;" : "=l"(d) : "l"(a), "l"(b), "l"(c));
    return d;
}
static __device__ __forceinline__ ull dup2(float w) {
    ull d;
    asm("mov.b64 %0, {%1, %1};" : "=l"(d) : "f"(w));
    return d;
}
static __device__ __forceinline__ ull pack2(float x, float y) {
    ull d;
    asm("mov.b64 %0, {%1, %2};" : "=l"(d) : "f"(x), "f"(y));
    return d;
}
static __device__ __forceinline__ float lo2(ull v) {
    return __uint_as_float((unsigned int)v);
}
static __device__ __forceinline__ float hi2(ull v) {
    return __uint_as_float((unsigned int)(v >> 32));
}

// ---------------- cp.async helpers ----------------
static __device__ __forceinline__ void cp16(void* dst, const void* src) {
    unsigned s = (unsigned)__cvta_generic_to_shared(dst);
    asm volatile("cp.async.cg.shared.global [%0], [%1], 16;" :: "r"(s), "l"(src));
}
static __device__ __forceinline__ void cp4(void* dst, const void* src) {
    unsigned s = (unsigned)__cvta_generic_to_shared(dst);
    asm volatile("cp.async.ca.shared.global [%0], [%1], 4;" :: "r"(s), "l"(src));
}
#define CP_COMMIT() asm volatile("cp.async.commit_group;")
#define CP_WAIT1()  asm volatile("cp.async.wait_group 1;")
#define CP_WAIT0()  asm volatile("cp.async.wait_group 0;")

// ==================== K1 (R11 exact, ~44us measured) ====================
#define K1_BM 64
#define K1_KC 32
#define K1_AS 66
#define K1_WS 33
#define K1_SMEM (K1_KC*K1_AS*4 + NOUT*K1_WS*4)   // 29568B

__global__ void __launch_bounds__(256, 2) k1_qh(
        const float* __restrict__ st,
        const float* __restrict__ Wq,
        const float* __restrict__ Sw1,
        const float* __restrict__ Sb1,
        const float* __restrict__ Sw2,
        const float* __restrict__ Sb2) {
    extern __shared__ float smem[];
    float* As = smem;                          // [32 k][66]
    float* Ws = smem + K1_KC * K1_AS;          // [160 n][33]

    const int tid = threadIdx.x;
    const int rt  = tid >> 5;
    const int ct  = tid & 31;
    const int row0 = blockIdx.x * K1_BM;

    const float* wp0 = Ws + (ct)       * K1_WS;
    const float* wp1 = Ws + (ct + 32)  * K1_WS;
    const float* wp2 = Ws + (ct + 64)  * K1_WS;
    const float* wp3 = Ws + (ct + 96)  * K1_WS;
    const float* wp4 = Ws + (ct + 128) * K1_WS;

    ull acc[4][5];
#pragma unroll
    for (int i = 0; i < 4; i++)
#pragma unroll
        for (int j = 0; j < 5; j++) acc[i][j] = 0ULL;

    for (int kc = 0; kc < S_DIM; kc += K1_KC) {
        __syncthreads();
#pragma unroll
        for (int s = 0; s < 2; s++) {
            int idx = tid + 256 * s;
            int row = idx >> 3, kq = idx & 7;
            float4 v = *(const float4*)(st + (size_t)(row0 + row) * S_DIM + kc + 4 * kq);
            As[(4 * kq + 0) * K1_AS + row] = v.x;
            As[(4 * kq + 1) * K1_AS + row] = v.y;
            As[(4 * kq + 2) * K1_AS + row] = v.z;
            As[(4 * kq + 3) * K1_AS + row] = v.w;
        }
        for (int i = tid; i < (NOUT * K1_KC) / 4; i += 256) {
            int n = i >> 3, kq = i & 7;
            const float* src = (n < 128) ? (Wq + n * S_DIM) : (Sw1 + (n - 128) * S_DIM);
            float4 v = *(const float4*)(src + kc + 4 * kq);
            Ws[n * K1_WS + 4 * kq + 0] = v.x;
            Ws[n * K1_WS + 4 * kq + 1] = v.y;
            Ws[n * K1_WS + 4 * kq + 2] = v.z;
            Ws[n * K1_WS + 4 * kq + 3] = v.w;
        }
        __syncthreads();

        float c0 = wp0[0], c1 = wp1[0], c2 = wp2[0], c3 = wp3[0], c4 = wp4[0];
        const float* ar0 = As + rt * 8;
        ull a0 = *(const ull*)(ar0);
        ull a1 = *(const ull*)(ar0 + 2);
        ull a2 = *(const ull*)(ar0 + 4);
        ull a3 = *(const ull*)(ar0 + 6);
#pragma unroll
        for (int kk = 0; kk < K1_KC; kk++) {
            float d0, d1, d2, d3, d4;
            ull e0, e1, e2, e3;
            if (kk < K1_KC - 1) {
                d0 = wp0[kk + 1]; d1 = wp1[kk + 1]; d2 = wp2[kk + 1];
                d3 = wp3[kk + 1]; d4 = wp4[kk + 1];
                const float* arn = As + (kk + 1) * K1_AS + rt * 8;
                e0 = *(const ull*)(arn);
                e1 = *(const ull*)(arn + 2);
                e2 = *(const ull*)(arn + 4);
                e3 = *(const ull*)(arn + 6);
            } else {
                d0 = d1 = d2 = d3 = d4 = 0.0f;
                e0 = e1 = e2 = e3 = 0ULL;
            }
            ull b0 = dup2(c0), b1 = dup2(c1), b2 = dup2(c2),
                b3 = dup2(c3), b4 = dup2(c4);
            acc[0][0] = fma2(a0, b0, acc[0][0]);
            acc[1][0] = fma2(a1, b0, acc[1][0]);
            acc[2][0] = fma2(a2, b0, acc[2][0]);
            acc[3][0] = fma2(a3, b0, acc[3][0]);
            acc[0][1] = fma2(a0, b1, acc[0][1]);
            acc[1][1] = fma2(a1, b1, acc[1][1]);
            acc[2][1] = fma2(a2, b1, acc[2][1]);
            acc[3][1] = fma2(a3, b1, acc[3][1]);
            acc[0][2] = fma2(a0, b2, acc[0][2]);
            acc[1][2] = fma2(a1, b2, acc[1][2]);
            acc[2][2] = fma2(a2, b2, acc[2][2]);
            acc[3][2] = fma2(a3, b2, acc[3][2]);
            acc[0][3] = fma2(a0, b3, acc[0][3]);
            acc[1][3] = fma2(a1, b3, acc[1][3]);
            acc[2][3] = fma2(a2, b3, acc[2][3]);
            acc[3][3] = fma2(a3, b3, acc[3][3]);
            acc[0][4] = fma2(a0, b4, acc[0][4]);
            acc[1][4] = fma2(a1, b4, acc[1][4]);
            acc[2][4] = fma2(a2, b4, acc[2][4]);
            acc[3][4] = fma2(a3, b4, acc[3][4]);
            c0 = d0; c1 = d1; c2 = d2; c3 = d3; c4 = d4;
            a0 = e0; a1 = e1; a2 = e2; a3 = e3;
        }
    }

    const float b1c = Sb1[ct];
    const float w2c = Sw2[ct];
    const float b2c = Sb2[0];
#pragma unroll
    for (int i = 0; i < 4; i++) {
        int r0 = row0 + rt * 8 + 2 * i;
#pragma unroll
        for (int j = 0; j < 4; j++) {
            g_qh[(size_t)r0 * 128 + ct + 32 * j]       = fmaxf(lo2(acc[i][j]), 0.0f);
            g_qh[(size_t)(r0 + 1) * 128 + ct + 32 * j] = fmaxf(hi2(acc[i][j]), 0.0f);
        }
        float h0 = fmaxf(lo2(acc[i][4]) + b1c, 0.0f) * w2c;
        float h1 = fmaxf(hi2(acc[i][4]) + b1c, 0.0f) * w2c;
#pragma unroll
        for (int d = 16; d > 0; d >>= 1) {
            h0 += __shfl_xor_sync(0xffffffffu, h0, d);
            h1 += __shfl_xor_sync(0xffffffffu, h1, d);
        }
        if (ct == 0) {
            g_v[r0]     = h0 + b2c;
            g_v[r0 + 1] = h1 + b2c;
        }
    }
}

// ==================== K2 (R11 exact) ====================
#define K2_BM 32

__global__ void __launch_bounds__(256) k2_p(const float* __restrict__ Wk) {
    __shared__ float qh_s[K2_BM * 128];

    const int tid = threadIdx.x;
    const int rt  = tid >> 5;
    const int ct  = tid & 31;
    const int row0 = blockIdx.x * K2_BM;

#pragma unroll
    for (int s = 0; s < 4; s++) {
        int i = tid + 256 * s;
        ((float4*)qh_s)[i] = *(const float4*)(g_qh + (size_t)row0 * 128 + 4 * i);
    }
    __syncthreads();

    const ull* wkp = (const ull*)Wk;
    ull* gp2 = (ull*)g_p;
#pragma unroll
    for (int h = 0; h < 4; h++) {
        ull acc[4][2];
#pragma unroll
        for (int rr = 0; rr < 4; rr++) { acc[rr][0] = 0ULL; acc[rr][1] = 0ULL; }

#pragma unroll 4
        for (int e4 = 0; e4 < 8; e4++) {
            float4 aq[4];
#pragma unroll
            for (int rr = 0; rr < 4; rr++)
                aq[rr] = *(const float4*)(qh_s + (rt * 4 + rr) * 128 + h * 32 + 4 * e4);
#pragma unroll
            for (int q = 0; q < 4; q++) {
                const ull* brow = wkp + (size_t)(h * 32 + 4 * e4 + q) * 64;
                ull b0 = brow[ct];
                ull b1 = brow[32 + ct];
#pragma unroll
                for (int rr = 0; rr < 4; rr++) {
                    float av = (q == 0) ? aq[rr].x : (q == 1) ? aq[rr].y
                             : (q == 2) ? aq[rr].z : aq[rr].w;
                    ull a = dup2(av);
                    acc[rr][0] = fma2(a, b0, acc[rr][0]);
                    acc[rr][1] = fma2(a, b1, acc[rr][1]);
                }
            }
        }
#pragma unroll
        for (int rr = 0; rr < 4; rr++) {
            size_t base = (size_t)(row0 + rt * 4 + rr) * 256 + h * 64;
            gp2[base + ct]      = acc[rr][0];
            gp2[base + 32 + ct] = acc[rr][1];
        }
    }
}

// ==================== K3: slim smem (no z buffer) + cp.async pipeline ====================
#define K3_ROWS 8

struct K3S {
    float4 ob[2][32 * 33];     // 33792B : ob[n][c] padded 33
    float4 pb[2][128];         //  4096B
    float  part_s[4][4][32];   //  2048B
    float  att_s[128];
    float  w_s[32];
    float  qv_s[32];
    float  vbuf[2];
};
#define K3_SMEM ((int)sizeof(K3S))    // ~40.8KB -> 5 CTAs/SM

__global__ void __launch_bounds__(128) k3_out(
        const float* __restrict__ z,
        const float* __restrict__ obs,
        float* __restrict__ out) {
    extern __shared__ char sm3[];
    K3S* S = (K3S*)sm3;

    const int tid = threadIdx.x;
    const size_t r0 = (size_t)blockIdx.x * K3_ROWS;
    const float4* gp4 = (const float4*)g_p;

    auto prefetch = [&](int b, size_t r) {
        const float4* obr4 = (const float4*)(obs + r * (size_t)(N_DIM * O_DIM));
#pragma unroll
        for (int seg = 0; seg < 8; seg++) {
            int i = tid + 128 * seg;
            int n = i >> 5, c = i & 31;
            cp16(&S->ob[b][n * 33 + c], obr4 + i);
        }
        cp16(&S->pb[b][tid], gp4 + r * 128 + tid);
        if (tid == 0) cp4(&S->vbuf[b], g_v + r);
    };

    prefetch(0, r0);
    CP_COMMIT();

    const int n  = tid & 31;
    const int oq = tid >> 5;

    for (int i = 0; i < K3_ROWS; i++) {
        const int b = i & 1;
        const size_t r = r0 + i;
        const float* zr = z + r * (size_t)(N_DIM * NQ_DIM);
        const float4* zr4 = (const float4*)zr;

        if (i + 1 < K3_ROWS) {
            prefetch(b ^ 1, r + 1);
            CP_COMMIT();
        }

        // q_vals from GLOBAL z (overlaps cp.async wait). thread t: row nq = t>>2,
        // quarter qq = t&3 -> 4 float4 each; 4-lane shfl reduce.
        {
            int nq = tid >> 2, qq = tid & 3;
            float s = 0.0f;
#pragma unroll
            for (int j = 0; j < 4; j++) {
                float4 v = zr4[nq * 16 + qq * 4 + j];
                s += v.x + v.y + v.z + v.w;
            }
            s += __shfl_xor_sync(0xffffffffu, s, 1);
            s += __shfl_xor_sync(0xffffffffu, s, 2);
            if (qq == 0) S->qv_s[nq] = s * (1.0f / 64.0f);
        }

        if (i + 1 < K3_ROWS) { CP_WAIT1(); } else { CP_WAIT0(); }
        __syncthreads();

        // scores: p via warp-uniform LDS.64 pairs, accumulate with fma2
        const ull* pu = (const ull*)S->pb[b];
        const float4* obn = &S->ob[b][n * 33 + oq * 8];
        ull ac0 = 0ULL, ac1 = 0ULL, ac2 = 0ULL, ac3 = 0ULL;
#pragma unroll
        for (int o4 = 0; o4 < 8; o4++) {
            float4 x = obn[o4];
            ull xa = pack2(x.x, x.y);
            ull xb = pack2(x.z, x.w);
            int pi = oq * 16 + 2 * o4;
            ac0 = fma2(xa, pu[0   + pi], ac0);
            ac0 = fma2(xb, pu[0   + pi + 1], ac0);
            ac1 = fma2(xa, pu[64  + pi], ac1);
            ac1 = fma2(xb, pu[64  + pi + 1], ac1);
            ac2 = fma2(xa, pu[128 + pi], ac2);
            ac2 = fma2(xb, pu[128 + pi + 1], ac2);
            ac3 = fma2(xa, pu[192 + pi], ac3);
            ac3 = fma2(xb, pu[192 + pi + 1], ac3);
        }
        S->part_s[oq][0][n] = lo2(ac0) + hi2(ac0);
        S->part_s[oq][1][n] = lo2(ac1) + hi2(ac1);
        S->part_s[oq][2][n] = lo2(ac2) + hi2(ac2);
        S->part_s[oq][3][n] = lo2(ac3) + hi2(ac3);
        __syncthreads();

        // softmax per head-warp (h = oq)
        const int h = oq;
        float s = S->part_s[0][h][n] + S->part_s[1][h][n]
                + S->part_s[2][h][n] + S->part_s[3][h][n];
        s *= INV_SQRT_E;
        if (S->qv_s[n] <= MASK_VAL) s = MASK_VAL;
        float m = s;
#pragma unroll
        for (int d = 16; d > 0; d >>= 1) m = fmaxf(m, __shfl_xor_sync(0xffffffffu, m, d));
        float ex = __expf(s - m);
        float ssum = ex;
#pragma unroll
        for (int d = 16; d > 0; d >>= 1) ssum += __shfl_xor_sync(0xffffffffu, ssum, d);
        S->att_s[h * 32 + n] = ex / ssum;
        __syncthreads();

        if (tid < 32)
            S->w_s[tid] = S->att_s[tid] + S->att_s[32 + tid]
                        + S->att_s[64 + tid] + S->att_s[96 + tid] + 1e-10f;
        __syncthreads();

        // out[q] = sum_n w[n]*z[n][q] + 32*v   (z reread from global; L1-hot)
        if (tid < 64) {
            float acc = (float)N_DIM * S->vbuf[b];
#pragma unroll
            for (int nn = 0; nn < 32; nn++)
                acc = fmaf(S->w_s[nn], __ldg(zr + nn * 64 + tid), acc);
            out[r * 64 + tid] = acc;
        }
        __syncthreads();
    }
}

// ==================== launch ====================
extern "C" void kernel_launch(void* const* d_in, const int* in_sizes, int n_in,
                              void* d_out, int out_size) {
    (void)in_sizes; (void)n_in; (void)out_size;
    const float* z   = (const float*)d_in[0];
    const float* st  = (const float*)d_in[1];
    const float* obs = (const float*)d_in[2];
    const float* Wq  = (const float*)d_in[3];
    const float* Wk  = (const float*)d_in[4];
    const float* Sw1 = (const float*)d_in[5];
    const float* Sb1 = (const float*)d_in[6];
    const float* Sw2 = (const float*)d_in[7];
    const float* Sb2 = (const float*)d_in[8];
    float* out = (float*)d_out;

    cudaFuncSetAttribute(k1_qh,  cudaFuncAttributeMaxDynamicSharedMemorySize, K1_SMEM);
    cudaFuncSetAttribute(k3_out, cudaFuncAttributeMaxDynamicSharedMemorySize, K3_SMEM);

    k1_qh<<<BT / K1_BM, 256, K1_SMEM>>>(st, Wq, Sw1, Sb1, Sw2, Sb2);
    k2_p<<<BT / K2_BM, 256>>>(Wk);
    k3_out<<<BT / K3_ROWS, 128, K3_SMEM>>>(z, obs, out);
}

// round 15
// speedup vs baseline: 1.0835x; 1.0810x over previous
#include <cuda_runtime.h>

// Problem constants
#define BT     16384
#define S_DIM  256
#define O_DIM  128
#define N_DIM  32
#define NQ_DIM 64
#define NOUT   160
#define MASK_VAL (-999999.0f)
#define INV_SQRT_E 0.17677669529663687f

typedef unsigned long long ull;

// Scratch (device globals; no allocation allowed)
__device__ float g_qh[(size_t)BT * 128];
__device__ float g_v[BT];
__device__ float g_p[(size_t)BT * 512];

// ---------------- packed f32x2 helpers ----------------
static __device__ __forceinline__ ull fma2(ull a, ull b, ull c) {
    ull d;
    asm("fma.rn.f32x2 %0, %1, %2, %3;" : "=l"(d) : "l"(a), "l"(b), "l"(c));
    return d;
}
static __device__ __forceinline__ ull dup2(float w) {
    ull d;
    asm("mov.b64 %0, {%1, %1};" : "=l"(d) : "f"(w));
    return d;
}
static __device__ __forceinline__ float lo2(ull v) {
    return __uint_as_float((unsigned int)v);
}
static __device__ __forceinline__ float hi2(ull v) {
    return __uint_as_float((unsigned int)(v >> 32));
}

// ---------------- cp.async helpers ----------------
static __device__ __forceinline__ void cp16(void* dst, const void* src) {
    unsigned s = (unsigned)__cvta_generic_to_shared(dst);
    asm volatile("cp.async.cg.shared.global [%0], [%1], 16;" :: "r"(s), "l"(src));
}
static __device__ __forceinline__ void cp4(void* dst, const void* src) {
    unsigned s = (unsigned)__cvta_generic_to_shared(dst);
    asm volatile("cp.async.ca.shared.global [%0], [%1], 4;" :: "r"(s), "l"(src));
}
#define CP_COMMIT() asm volatile("cp.async.commit_group;")
#define CP_WAIT1()  asm volatile("cp.async.wait_group 1;")
#define CP_WAIT0()  asm volatile("cp.async.wait_group 0;")

// ==================== K1 (R11 exact, ~44us measured) ====================
#define K1_BM 64
#define K1_KC 32
#define K1_AS 66
#define K1_WS 33
#define K1_SMEM (K1_KC*K1_AS*4 + NOUT*K1_WS*4)   // 29568B

__global__ void __launch_bounds__(256, 2) k1_qh(
        const float* __restrict__ st,
        const float* __restrict__ Wq,
        const float* __restrict__ Sw1,
        const float* __restrict__ Sb1,
        const float* __restrict__ Sw2,
        const float* __restrict__ Sb2) {
    extern __shared__ float smem[];
    float* As = smem;                          // [32 k][66]
    float* Ws = smem + K1_KC * K1_AS;          // [160 n][33]

    const int tid = threadIdx.x;
    const int rt  = tid >> 5;
    const int ct  = tid & 31;
    const int row0 = blockIdx.x * K1_BM;

    const float* wp0 = Ws + (ct)       * K1_WS;
    const float* wp1 = Ws + (ct + 32)  * K1_WS;
    const float* wp2 = Ws + (ct + 64)  * K1_WS;
    const float* wp3 = Ws + (ct + 96)  * K1_WS;
    const float* wp4 = Ws + (ct + 128) * K1_WS;

    ull acc[4][5];
#pragma unroll
    for (int i = 0; i < 4; i++)
#pragma unroll
        for (int j = 0; j < 5; j++) acc[i][j] = 0ULL;

    for (int kc = 0; kc < S_DIM; kc += K1_KC) {
        __syncthreads();
#pragma unroll
        for (int s = 0; s < 2; s++) {
            int idx = tid + 256 * s;
            int row = idx >> 3, kq = idx & 7;
            float4 v = *(const float4*)(st + (size_t)(row0 + row) * S_DIM + kc + 4 * kq);
            As[(4 * kq + 0) * K1_AS + row] = v.x;
            As[(4 * kq + 1) * K1_AS + row] = v.y;
            As[(4 * kq + 2) * K1_AS + row] = v.z;
            As[(4 * kq + 3) * K1_AS + row] = v.w;
        }
        for (int i = tid; i < (NOUT * K1_KC) / 4; i += 256) {
            int n = i >> 3, kq = i & 7;
            const float* src = (n < 128) ? (Wq + n * S_DIM) : (Sw1 + (n - 128) * S_DIM);
            float4 v = *(const float4*)(src + kc + 4 * kq);
            Ws[n * K1_WS + 4 * kq + 0] = v.x;
            Ws[n * K1_WS + 4 * kq + 1] = v.y;
            Ws[n * K1_WS + 4 * kq + 2] = v.z;
            Ws[n * K1_WS + 4 * kq + 3] = v.w;
        }
        __syncthreads();

        float c0 = wp0[0], c1 = wp1[0], c2 = wp2[0], c3 = wp3[0], c4 = wp4[0];
        const float* ar0 = As + rt * 8;
        ull a0 = *(const ull*)(ar0);
        ull a1 = *(const ull*)(ar0 + 2);
        ull a2 = *(const ull*)(ar0 + 4);
        ull a3 = *(const ull*)(ar0 + 6);
#pragma unroll
        for (int kk = 0; kk < K1_KC; kk++) {
            float d0, d1, d2, d3, d4;
            ull e0, e1, e2, e3;
            if (kk < K1_KC - 1) {
                d0 = wp0[kk + 1]; d1 = wp1[kk + 1]; d2 = wp2[kk + 1];
                d3 = wp3[kk + 1]; d4 = wp4[kk + 1];
                const float* arn = As + (kk + 1) * K1_AS + rt * 8;
                e0 = *(const ull*)(arn);
                e1 = *(const ull*)(arn + 2);
                e2 = *(const ull*)(arn + 4);
                e3 = *(const ull*)(arn + 6);
            } else {
                d0 = d1 = d2 = d3 = d4 = 0.0f;
                e0 = e1 = e2 = e3 = 0ULL;
            }
            ull b0 = dup2(c0), b1 = dup2(c1), b2 = dup2(c2),
                b3 = dup2(c3), b4 = dup2(c4);
            acc[0][0] = fma2(a0, b0, acc[0][0]);
            acc[1][0] = fma2(a1, b0, acc[1][0]);
            acc[2][0] = fma2(a2, b0, acc[2][0]);
            acc[3][0] = fma2(a3, b0, acc[3][0]);
            acc[0][1] = fma2(a0, b1, acc[0][1]);
            acc[1][1] = fma2(a1, b1, acc[1][1]);
            acc[2][1] = fma2(a2, b1, acc[2][1]);
            acc[3][1] = fma2(a3, b1, acc[3][1]);
            acc[0][2] = fma2(a0, b2, acc[0][2]);
            acc[1][2] = fma2(a1, b2, acc[1][2]);
            acc[2][2] = fma2(a2, b2, acc[2][2]);
            acc[3][2] = fma2(a3, b2, acc[3][2]);
            acc[0][3] = fma2(a0, b3, acc[0][3]);
            acc[1][3] = fma2(a1, b3, acc[1][3]);
            acc[2][3] = fma2(a2, b3, acc[2][3]);
            acc[3][3] = fma2(a3, b3, acc[3][3]);
            acc[0][4] = fma2(a0, b4, acc[0][4]);
            acc[1][4] = fma2(a1, b4, acc[1][4]);
            acc[2][4] = fma2(a2, b4, acc[2][4]);
            acc[3][4] = fma2(a3, b4, acc[3][4]);
            c0 = d0; c1 = d1; c2 = d2; c3 = d3; c4 = d4;
            a0 = e0; a1 = e1; a2 = e2; a3 = e3;
        }
    }

    const float b1c = Sb1[ct];
    const float w2c = Sw2[ct];
    const float b2c = Sb2[0];
#pragma unroll
    for (int i = 0; i < 4; i++) {
        int r0 = row0 + rt * 8 + 2 * i;
#pragma unroll
        for (int j = 0; j < 4; j++) {
            g_qh[(size_t)r0 * 128 + ct + 32 * j]       = fmaxf(lo2(acc[i][j]), 0.0f);
            g_qh[(size_t)(r0 + 1) * 128 + ct + 32 * j] = fmaxf(hi2(acc[i][j]), 0.0f);
        }
        float h0 = fmaxf(lo2(acc[i][4]) + b1c, 0.0f) * w2c;
        float h1 = fmaxf(hi2(acc[i][4]) + b1c, 0.0f) * w2c;
#pragma unroll
        for (int d = 16; d > 0; d >>= 1) {
            h0 += __shfl_xor_sync(0xffffffffu, h0, d);
            h1 += __shfl_xor_sync(0xffffffffu, h1, d);
        }
        if (ct == 0) {
            g_v[r0]     = h0 + b2c;
            g_v[r0 + 1] = h1 + b2c;
        }
    }
}

// ==================== K2 (R11 exact) ====================
#define K2_BM 32

__global__ void __launch_bounds__(256) k2_p(const float* __restrict__ Wk) {
    __shared__ float qh_s[K2_BM * 128];

    const int tid = threadIdx.x;
    const int rt  = tid >> 5;
    const int ct  = tid & 31;
    const int row0 = blockIdx.x * K2_BM;

#pragma unroll
    for (int s = 0; s < 4; s++) {
        int i = tid + 256 * s;
        ((float4*)qh_s)[i] = *(const float4*)(g_qh + (size_t)row0 * 128 + 4 * i);
    }
    __syncthreads();

    const ull* wkp = (const ull*)Wk;
    ull* gp2 = (ull*)g_p;
#pragma unroll
    for (int h = 0; h < 4; h++) {
        ull acc[4][2];
#pragma unroll
        for (int rr = 0; rr < 4; rr++) { acc[rr][0] = 0ULL; acc[rr][1] = 0ULL; }

#pragma unroll 4
        for (int e4 = 0; e4 < 8; e4++) {
            float4 aq[4];
#pragma unroll
            for (int rr = 0; rr < 4; rr++)
                aq[rr] = *(const float4*)(qh_s + (rt * 4 + rr) * 128 + h * 32 + 4 * e4);
#pragma unroll
            for (int q = 0; q < 4; q++) {
                const ull* brow = wkp + (size_t)(h * 32 + 4 * e4 + q) * 64;
                ull b0 = brow[ct];
                ull b1 = brow[32 + ct];
#pragma unroll
                for (int rr = 0; rr < 4; rr++) {
                    float av = (q == 0) ? aq[rr].x : (q == 1) ? aq[rr].y
                             : (q == 2) ? aq[rr].z : aq[rr].w;
                    ull a = dup2(av);
                    acc[rr][0] = fma2(a, b0, acc[rr][0]);
                    acc[rr][1] = fma2(a, b1, acc[rr][1]);
                }
            }
        }
#pragma unroll
        for (int rr = 0; rr < 4; rr++) {
            size_t base = (size_t)(row0 + rt * 4 + rr) * 256 + h * 64;
            gp2[base + ct]      = acc[rr][0];
            gp2[base + 32 + ct] = acc[rr][1];
        }
    }
}

// ==================== K3: R11 algorithm, 256 threads per row ====================
#define K3_ROWS 8

struct K3S {
    float4 ob[2][32 * 33];     // ob[n][c] padded 33 (R11 layout)
    float4 zb[2][32 * 17];     // z[n][jq] padded 17 (R11 layout)
    float4 pb[2][128];
    float  part_s[8][4][32];   // 8 o-chunks of 16
    float  att_s[128];
    float  w_s[32];
    float  qv_s[32];
    float  vbuf[2];
};
#define K3_SMEM ((int)sizeof(K3S))   // ~60KB -> 3 CTAs/SM, 24 warps/SM

__global__ void __launch_bounds__(256) k3_out(
        const float* __restrict__ z,
        const float* __restrict__ obs,
        float* __restrict__ out) {
    extern __shared__ char sm3[];
    K3S* S = (K3S*)sm3;

    const int tid = threadIdx.x;
    const size_t r0 = (size_t)blockIdx.x * K3_ROWS;
    const float4* gp4 = (const float4*)g_p;

    auto prefetch = [&](int b, size_t r) {
        const float4* obr4 = (const float4*)(obs + r * (size_t)(N_DIM * O_DIM));
        const float4* zr4  = (const float4*)(z + r * (size_t)(N_DIM * NQ_DIM));
#pragma unroll
        for (int seg = 0; seg < 4; seg++) {           // ob: 1024 f4
            int i = tid + 256 * seg;
            int n = i >> 5, c = i & 31;
            cp16(&S->ob[b][n * 33 + c], obr4 + i);
        }
#pragma unroll
        for (int seg = 0; seg < 2; seg++) {           // zb: 512 f4
            int i = tid + 256 * seg;
            int n = i >> 4, jq = i & 15;
            cp16(&S->zb[b][n * 17 + jq], zr4 + i);
        }
        if (tid < 128) cp16(&S->pb[b][tid], gp4 + r * 128 + tid);
        if (tid == 0) cp4(&S->vbuf[b], g_v + r);
    };

    prefetch(0, r0);
    CP_COMMIT();

    const int n  = tid & 31;
    const int oc = tid >> 5;          // 8 o-chunks of 16

    for (int i = 0; i < K3_ROWS; i++) {
        const int b = i & 1;
        const size_t r = r0 + i;
        if (i + 1 < K3_ROWS) {
            prefetch(b ^ 1, r + 1);
            CP_COMMIT();
            CP_WAIT1();
        } else {
            CP_WAIT0();
        }
        __syncthreads();

        // q_vals over 2 warps: thread t<64: row n2 = t>>1, half hf = t&1
        if (tid < 64) {
            int n2 = tid >> 1, hf = tid & 1;
            const float4* zrow = &S->zb[b][n2 * 17 + hf * 8];
            float s = 0.0f;
#pragma unroll
            for (int j = 0; j < 8; j++) {
                float4 v = zrow[j];
                s += v.x + v.y + v.z + v.w;
            }
            s += __shfl_xor_sync(0xffffffffu, s, 1);
            if (hf == 0) S->qv_s[n2] = s * (1.0f / 64.0f);
        }

        // scores: thread (n, oc) covers o in [oc*16, oc*16+16) — 4 float4
        const float4* obn = &S->ob[b][n * 33 + oc * 4];
        const float4* pbv = S->pb[b];
        float pa0 = 0.0f, pa1 = 0.0f, pa2 = 0.0f, pa3 = 0.0f;
#pragma unroll
        for (int o4 = 0; o4 < 4; o4++) {
            float4 x  = obn[o4];
            float4 p0 = pbv[0  + oc * 4 + o4];
            float4 p1 = pbv[32 + oc * 4 + o4];
            float4 p2 = pbv[64 + oc * 4 + o4];
            float4 p3 = pbv[96 + oc * 4 + o4];
            pa0 += x.x * p0.x + x.y * p0.y + x.z * p0.z + x.w * p0.w;
            pa1 += x.x * p1.x + x.y * p1.y + x.z * p1.z + x.w * p1.w;
            pa2 += x.x * p2.x + x.y * p2.y + x.z * p2.z + x.w * p2.w;
            pa3 += x.x * p3.x + x.y * p3.y + x.z * p3.z + x.w * p3.w;
        }
        S->part_s[oc][0][n] = pa0;
        S->part_s[oc][1][n] = pa1;
        S->part_s[oc][2][n] = pa2;
        S->part_s[oc][3][n] = pa3;
        __syncthreads();

        // softmax: warps 0-3, warp h handles head h (warps 4-7 idle this phase)
        if (tid < 128) {
            const int h = oc;     // oc<4 here
            float s = 0.0f;
#pragma unroll
            for (int c = 0; c < 8; c++) s += S->part_s[c][h][n];
            s *= INV_SQRT_E;
            if (S->qv_s[n] <= MASK_VAL) s = MASK_VAL;
            float m = s;
#pragma unroll
            for (int d = 16; d > 0; d >>= 1)
                m = fmaxf(m, __shfl_xor_sync(0xffffffffu, m, d));
            float ex = __expf(s - m);
            float ssum = ex;
#pragma unroll
            for (int d = 16; d > 0; d >>= 1)
                ssum += __shfl_xor_sync(0xffffffffu, ssum, d);
            S->att_s[h * 32 + n] = ex / ssum;
        }
        __syncthreads();

        if (tid < 32)
            S->w_s[tid] = S->att_s[tid] + S->att_s[32 + tid]
                        + S->att_s[64 + tid] + S->att_s[96 + tid] + 1e-10f;
        __syncthreads();

        // out[q] = sum_n w[n]*z[n][q] + 32*v   (zb as floats, row stride 68)
        if (tid < 64) {
            const float* zsf = (const float*)S->zb[b];
            float acc = (float)N_DIM * S->vbuf[b];
#pragma unroll
            for (int nn = 0; nn < 32; nn++)
                acc = fmaf(S->w_s[nn], zsf[nn * 68 + tid], acc);
            out[r * 64 + tid] = acc;
        }
        __syncthreads();
    }
}

// ==================== launch ====================
extern "C" void kernel_launch(void* const* d_in, const int* in_sizes, int n_in,
                              void* d_out, int out_size) {
    (void)in_sizes; (void)n_in; (void)out_size;
    const float* z   = (const float*)d_in[0];
    const float* st  = (const float*)d_in[1];
    const float* obs = (const float*)d_in[2];
    const float* Wq  = (const float*)d_in[3];
    const float* Wk  = (const float*)d_in[4];
    const float* Sw1 = (const float*)d_in[5];
    const float* Sb1 = (const float*)d_in[6];
    const float* Sw2 = (const float*)d_in[7];
    const float* Sb2 = (const float*)d_in[8];
    float* out = (float*)d_out;

    cudaFuncSetAttribute(k1_qh,  cudaFuncAttributeMaxDynamicSharedMemorySize, K1_SMEM);
    cudaFuncSetAttribute(k3_out, cudaFuncAttributeMaxDynamicSharedMemorySize, K3_SMEM);

    k1_qh<<<BT / K1_BM, 256, K1_SMEM>>>(st, Wq, Sw1, Sb1, Sw2, Sb2);
    k2_p<<<BT / K2_BM, 256>>>(Wk);
    k3_out<<<BT / K3_ROWS, 256, K3_SMEM>>>(z, obs, out);
}